// round 9
// baseline (speedup 1.0000x reference)
#include <cuda_runtime.h>
#include <cuda_bf16.h>
#include <cstdint>

#define BATCH 8
#define SEQLEN 1024
#define DIN 512
#define NHEAD 8
#define HDIM 64
#define DOUT 512
#define MTOT (BATCH * SEQLEN)   // 8192
#define NBH (BATCH * NHEAD)     // 64

// ---------------------------------------------------------------------------
// Static device scratch (no runtime allocation allowed)
// ---------------------------------------------------------------------------
__device__ __align__(16) __nv_bfloat16 g_xhi[3 * MTOT * DIN];
__device__ __align__(16) __nv_bfloat16 g_xlo[3 * MTOT * DIN];
__device__ __align__(16) __nv_bfloat16 g_wthi[3 * DOUT * DIN];
__device__ __align__(16) __nv_bfloat16 g_wtlo[3 * DOUT * DIN];

// projected q/k/v, head-major [bh][l][64], bf16 hi/lo
__device__ __align__(16) __nv_bfloat16 g_qhi[NBH * SEQLEN * HDIM];
__device__ __align__(16) __nv_bfloat16 g_qlo[NBH * SEQLEN * HDIM];
__device__ __align__(16) __nv_bfloat16 g_khi[NBH * SEQLEN * HDIM];
__device__ __align__(16) __nv_bfloat16 g_klo[NBH * SEQLEN * HDIM];
__device__ __align__(16) __nv_bfloat16 g_vhi[NBH * SEQLEN * HDIM];
__device__ __align__(16) __nv_bfloat16 g_vlo[NBH * SEQLEN * HDIM];

__device__ __forceinline__ void split_bf16(float x, __nv_bfloat16& h, __nv_bfloat16& l) {
    h = __float2bfloat16(x);
    l = __float2bfloat16(x - __bfloat162float(h));
}

__device__ __forceinline__ void mma16816(float* c, const uint32_t* a, const uint32_t* b) {
    asm volatile(
        "mma.sync.aligned.m16n8k16.row.col.f32.bf16.bf16.f32 "
        "{%0,%1,%2,%3}, {%4,%5,%6,%7}, {%8,%9}, {%0,%1,%2,%3};"
        : "+f"(c[0]), "+f"(c[1]), "+f"(c[2]), "+f"(c[3])
        : "r"(a[0]), "r"(a[1]), "r"(a[2]), "r"(a[3]), "r"(b[0]), "r"(b[1]));
}

__device__ __forceinline__ void ldsm4(uint32_t* r, const __nv_bfloat16* p) {
    uint32_t a = (uint32_t)__cvta_generic_to_shared(p);
    asm volatile("ldmatrix.sync.aligned.m8n8.x4.shared.b16 {%0,%1,%2,%3}, [%4];"
        : "=r"(r[0]), "=r"(r[1]), "=r"(r[2]), "=r"(r[3]) : "r"(a));
}
__device__ __forceinline__ void ldsm4t(uint32_t* r, const __nv_bfloat16* p) {
    uint32_t a = (uint32_t)__cvta_generic_to_shared(p);
    asm volatile("ldmatrix.sync.aligned.m8n8.x4.trans.shared.b16 {%0,%1,%2,%3}, [%4];"
        : "=r"(r[0]), "=r"(r[1]), "=r"(r[2]), "=r"(r[3]) : "r"(a));
}

// 16B global->shared async copy
__device__ __forceinline__ void cp16(void* smem_dst, const void* gsrc) {
    uint32_t sa = (uint32_t)__cvta_generic_to_shared(smem_dst);
    asm volatile("cp.async.cg.shared.global [%0], [%1], 16;" :: "r"(sa), "l"(gsrc));
}
#define CP_COMMIT() asm volatile("cp.async.commit_group;" ::: "memory")
#define CP_WAIT1()  asm volatile("cp.async.wait_group 1;" ::: "memory")
#define CP_WAIT0()  asm volatile("cp.async.wait_group 0;" ::: "memory")

// FMA-pipe exp2 (no MUFU), max rel err ~4e-5
__device__ __forceinline__ float fexp2(float t) {
    t = fmaxf(t, -126.0f);
    float z = t + 12582912.0f;
    int   i = __float_as_int(z) - 0x4B400000;
    float f = t - (z - 12582912.0f);
    float p = fmaf(f, 0.00961813f, 0.05550411f);
    p = fmaf(f, p, 0.24022651f);
    p = fmaf(f, p, 0.69314718f);
    p = fmaf(f, p, 1.0f);
    return p * __int_as_float((i + 127) << 23);
}
#define L2E 1.4426950408889634f

__device__ __forceinline__ void split_pack(float x, float y, uint32_t& hi, uint32_t& lo) {
    __nv_bfloat16 hx = __float2bfloat16(x), hy = __float2bfloat16(y);
    float rx = x - __bfloat162float(hx);
    float ry = y - __bfloat162float(hy);
    __nv_bfloat162 H(hx, hy);
    __nv_bfloat162 L(__float2bfloat16(rx), __float2bfloat16(ry));
    hi = *(uint32_t*)&H;
    lo = *(uint32_t*)&L;
}

// ---------------------------------------------------------------------------
// Conversion: X (fp32) -> bf16 hi/lo. 8 floats per thread, 16B stores.
// ---------------------------------------------------------------------------
__global__ __launch_bounds__(256) void convert_x(
    const float* __restrict__ x0, const float* __restrict__ x1,
    const float* __restrict__ x2)
{
    const int sel = blockIdx.y;
    const float* __restrict__ x = (sel == 0) ? x0 : (sel == 1) ? x1 : x2;
    const int i = blockIdx.x * 256 + threadIdx.x;
    const float4* xv = (const float4*)x;
    float4 a = xv[2 * i], b = xv[2 * i + 1];

    uint32_t h01, h23, h45, h67, l01, l23, l45, l67;
    split_pack(a.x, a.y, h01, l01);
    split_pack(a.z, a.w, h23, l23);
    split_pack(b.x, b.y, h45, l45);
    split_pack(b.z, b.w, h67, l67);

    const size_t e = (size_t)sel * (MTOT * DIN) + (size_t)i * 8;
    *(uint4*)&g_xhi[e] = make_uint4(h01, h23, h45, h67);
    *(uint4*)&g_xlo[e] = make_uint4(l01, l23, l45, l67);
}

__global__ __launch_bounds__(256) void convert_wt(
    const float* __restrict__ w0, const float* __restrict__ w1,
    const float* __restrict__ w2)
{
    const int sel = blockIdx.z;
    const float* __restrict__ W = (sel == 0) ? w0 : (sel == 1) ? w1 : w2;
    __shared__ float tile[32][33];
    const int n0 = blockIdx.x * 32, k0 = blockIdx.y * 32;
    const int tx = threadIdx.x, ty = threadIdx.y;
#pragma unroll
    for (int i = 0; i < 32; i += 8)
        tile[ty + i][tx] = W[(k0 + ty + i) * DOUT + n0 + tx];
    __syncthreads();
    const size_t base = (size_t)sel * (DOUT * DIN);
#pragma unroll
    for (int i = 0; i < 32; i += 8) {
        int n = ty + i;
        float v = tile[tx][n];
        __nv_bfloat16 h, l;
        split_bf16(v, h, l);
        g_wthi[base + (size_t)(n0 + n) * DIN + k0 + tx] = h;
        g_wtlo[base + (size_t)(n0 + n) * DIN + k0 + tx] = l;
    }
}

// ---------------------------------------------------------------------------
// Projection GEMM, bf16-split mma.sync, cp.async double buffer, ldmatrix frags.
// Epilogue writes q/k/v as bf16 hi/lo head-major.
// ---------------------------------------------------------------------------
#define PADK 40
#define PTILE (128 * PADK)
#define PBUF  (4 * PTILE)
#define PROJ_DSMEM (2 * PBUF * 2)

__global__ __launch_bounds__(256) void proj_mma_sync()
{
    extern __shared__ __align__(16) __nv_bfloat16 dsm[];

    const int sel = blockIdx.z;
    const int n0  = blockIdx.x * 128;
    const int m0  = blockIdx.y * 128;
    const int tid = threadIdx.x;
    const int w   = tid >> 5;
    const int lane = tid & 31;
    const int wm = w >> 2, wn = w & 3;
    const int lr = lane >> 2, lc = lane & 3;
    const int mi = lane >> 3, r8 = lane & 7;

    const __nv_bfloat16* __restrict__ Ahp = g_xhi + (size_t)sel * (MTOT * DIN);
    const __nv_bfloat16* __restrict__ Alp = g_xlo + (size_t)sel * (MTOT * DIN);
    const __nv_bfloat16* __restrict__ Bhp = g_wthi + (size_t)sel * (DOUT * DIN);
    const __nv_bfloat16* __restrict__ Blp = g_wtlo + (size_t)sel * (DOUT * DIN);

    const int r0 = tid >> 2, c0 = (tid & 3) * 8;
    const int r1 = (tid + 256) >> 2, c1 = ((tid + 256) & 3) * 8;

    auto issue = [&](int slab, int buf) {
        const int kk = slab * 32;
        __nv_bfloat16* base = dsm + buf * PBUF;
        const size_t ga0 = (size_t)(m0 + r0) * DIN + kk + c0;
        const size_t gb0 = (size_t)(n0 + r0) * DIN + kk + c0;
        const size_t ga1 = (size_t)(m0 + r1) * DIN + kk + c1;
        const size_t gb1 = (size_t)(n0 + r1) * DIN + kk + c1;
        cp16(base + 0 * PTILE + r0 * PADK + c0, Ahp + ga0);
        cp16(base + 1 * PTILE + r0 * PADK + c0, Alp + ga0);
        cp16(base + 2 * PTILE + r0 * PADK + c0, Bhp + gb0);
        cp16(base + 3 * PTILE + r0 * PADK + c0, Blp + gb0);
        cp16(base + 0 * PTILE + r1 * PADK + c1, Ahp + ga1);
        cp16(base + 1 * PTILE + r1 * PADK + c1, Alp + ga1);
        cp16(base + 2 * PTILE + r1 * PADK + c1, Bhp + gb1);
        cp16(base + 3 * PTILE + r1 * PADK + c1, Blp + gb1);
        CP_COMMIT();
    };

    // ldmatrix lane-address offsets
    const int bofs = (wn * 32 + r8) * PADK + 8 * mi;                    // B: nt stride 8*PADK
    const int aofs = (wm * 64 + (mi & 1) * 8 + r8) * PADK + (mi >> 1) * 8;  // A: mt stride 16*PADK, ks stride 16

    float acc[4][4][4];
#pragma unroll
    for (int i = 0; i < 4; i++)
#pragma unroll
        for (int j = 0; j < 4; j++)
#pragma unroll
            for (int r = 0; r < 4; r++) acc[i][j][r] = 0.f;

    issue(0, 0);

    for (int s = 0; s < DIN / 32; s++) {
        if (s + 1 < DIN / 32) { issue(s + 1, (s + 1) & 1); CP_WAIT1(); }
        else                  { CP_WAIT0(); }
        __syncthreads();

        const __nv_bfloat16* sAh = dsm + (s & 1) * PBUF + 0 * PTILE;
        const __nv_bfloat16* sAl = dsm + (s & 1) * PBUF + 1 * PTILE;
        const __nv_bfloat16* sBh = dsm + (s & 1) * PBUF + 2 * PTILE;
        const __nv_bfloat16* sBl = dsm + (s & 1) * PBUF + 3 * PTILE;

        // B fragments for the whole 32-wide slab: regs [2ks],[2ks+1] per nt
        uint32_t bH[4][4], bL[4][4];
#pragma unroll
        for (int nt = 0; nt < 4; nt++) {
            ldsm4(bH[nt], sBh + bofs + nt * 8 * PADK);
            ldsm4(bL[nt], sBl + bofs + nt * 8 * PADK);
        }

#pragma unroll
        for (int ks = 0; ks < 2; ks++) {
            uint32_t af[4][4];
#pragma unroll
            for (int mt = 0; mt < 4; mt++)
                ldsm4(af[mt], sAh + aofs + mt * 16 * PADK + ks * 16);
#pragma unroll
            for (int mt = 0; mt < 4; mt++)
#pragma unroll
                for (int nt = 0; nt < 4; nt++) {
                    mma16816(acc[mt][nt], af[mt], &bH[nt][2 * ks]);
                    mma16816(acc[mt][nt], af[mt], &bL[nt][2 * ks]);
                }
#pragma unroll
            for (int mt = 0; mt < 4; mt++)
                ldsm4(af[mt], sAl + aofs + mt * 16 * PADK + ks * 16);
#pragma unroll
            for (int mt = 0; mt < 4; mt++)
#pragma unroll
                for (int nt = 0; nt < 4; nt++)
                    mma16816(acc[mt][nt], af[mt], &bH[nt][2 * ks]);
        }
        __syncthreads();
    }

    // ---- unified epilogue: bf16 hi/lo head-major ----
    const float scale = (sel == 0) ? 0.125f : 1.0f;
    __nv_bfloat16* __restrict__ dh = (sel == 0) ? g_qhi : (sel == 1) ? g_khi : g_vhi;
    __nv_bfloat16* __restrict__ dl = (sel == 0) ? g_qlo : (sel == 1) ? g_klo : g_vlo;
#pragma unroll
    for (int mt = 0; mt < 4; mt++) {
#pragma unroll
        for (int half = 0; half < 2; half++) {
            int m = m0 + wm * 64 + mt * 16 + half * 8 + lr;
            int b = m >> 10;
            int l = m & 1023;
#pragma unroll
            for (int nt = 0; nt < 4; nt++) {
                int n = n0 + wn * 32 + nt * 8 + lc * 2;
                int h = n >> 6;
                int d = n & 63;
                uint32_t hi, lo;
                split_pack(acc[mt][nt][half * 2 + 0] * scale,
                           acc[mt][nt][half * 2 + 1] * scale, hi, lo);
                size_t off = (((size_t)(b * NHEAD + h) * SEQLEN) + l) * HDIM + d;
                *(uint32_t*)&dh[off] = hi;
                *(uint32_t*)&dl[off] = lo;
            }
        }
    }
}

// ---------------------------------------------------------------------------
// Flash attention on tensor cores; K and V both [key][d] row-major in smem,
// V transposed in the load unit via ldmatrix.trans.
// ---------------------------------------------------------------------------
#define AP 72
#define ATILE (64 * AP)
#define ABUF  (4 * ATILE)
#define ATTN_DSMEM (2 * ABUF * 2)

__global__ __launch_bounds__(256) void attn_mma(float* __restrict__ out)
{
    extern __shared__ __align__(16) __nv_bfloat16 adsm[];

    const int bh  = blockIdx.x & (NBH - 1);
    const int qb  = (SEQLEN / 128 - 1) - (blockIdx.x >> 6);
    const int q0  = qb * 128;
    const int tid = threadIdx.x;
    const int w    = tid >> 5;
    const int lane = tid & 31;
    const int lr = lane >> 2, lc = lane & 3;
    const int mi = lane >> 3, r8 = lane & 7;
    const int wr0 = q0 + w * 16;
    const int wlast = wr0 + 15;

    const size_t bhoff = (size_t)bh * (SEQLEN * HDIM);
    const __nv_bfloat16* __restrict__ Kh = g_khi + bhoff;
    const __nv_bfloat16* __restrict__ Kl = g_klo + bhoff;
    const __nv_bfloat16* __restrict__ Vh = g_vhi + bhoff;
    const __nv_bfloat16* __restrict__ Vl = g_vlo + bhoff;

    const int r0 = tid >> 3, c0 = (tid & 7) * 8;
    const int r1 = (tid + 256) >> 3, c1 = ((tid + 256) & 7) * 8;

    auto issue = [&](int tileidx, int buf) {
        const int k0 = tileidx * 64;
        __nv_bfloat16* base = adsm + buf * ABUF;
        const size_t g0 = (size_t)(k0 + r0) * HDIM + c0;
        const size_t g1 = (size_t)(k0 + r1) * HDIM + c1;
        cp16(base + 0 * ATILE + r0 * AP + c0, Kh + g0);
        cp16(base + 1 * ATILE + r0 * AP + c0, Kl + g0);
        cp16(base + 2 * ATILE + r0 * AP + c0, Vh + g0);
        cp16(base + 3 * ATILE + r0 * AP + c0, Vl + g0);
        cp16(base + 0 * ATILE + r1 * AP + c1, Kh + g1);
        cp16(base + 1 * ATILE + r1 * AP + c1, Kl + g1);
        cp16(base + 2 * ATILE + r1 * AP + c1, Vh + g1);
        cp16(base + 3 * ATILE + r1 * AP + c1, Vl + g1);
        CP_COMMIT();
    };

    uint32_t aQh[4][4], aQl[4][4];
    {
        const __nv_bfloat16* __restrict__ Qh = g_qhi + bhoff;
        const __nv_bfloat16* __restrict__ Ql = g_qlo + bhoff;
#pragma unroll
        for (int ks = 0; ks < 4; ks++) {
            int k = ks * 16 + 2 * lc;
            aQh[ks][0] = *(const uint32_t*)&Qh[(wr0 + lr) * HDIM + k];
            aQh[ks][1] = *(const uint32_t*)&Qh[(wr0 + 8 + lr) * HDIM + k];
            aQh[ks][2] = *(const uint32_t*)&Qh[(wr0 + lr) * HDIM + k + 8];
            aQh[ks][3] = *(const uint32_t*)&Qh[(wr0 + 8 + lr) * HDIM + k + 8];
            aQl[ks][0] = *(const uint32_t*)&Ql[(wr0 + lr) * HDIM + k];
            aQl[ks][1] = *(const uint32_t*)&Ql[(wr0 + 8 + lr) * HDIM + k];
            aQl[ks][2] = *(const uint32_t*)&Ql[(wr0 + lr) * HDIM + k + 8];
            aQl[ks][3] = *(const uint32_t*)&Ql[(wr0 + 8 + lr) * HDIM + k + 8];
        }
    }

    float o[8][4];
#pragma unroll
    for (int nt = 0; nt < 8; nt++)
#pragma unroll
        for (int j = 0; j < 4; j++) o[nt][j] = 0.f;
    float m0 = -1e30f, m1 = -1e30f, l0 = 0.f, l1 = 0.f;

    const int ntiles = (q0 + 128) / 64;
    issue(0, 0);

    for (int t = 0; t < ntiles; t++) {
        if (t + 1 < ntiles) { issue(t + 1, (t + 1) & 1); CP_WAIT1(); }
        else                { CP_WAIT0(); }
        __syncthreads();

        const __nv_bfloat16* sKh = adsm + (t & 1) * ABUF + 0 * ATILE;
        const __nv_bfloat16* sKl = adsm + (t & 1) * ABUF + 1 * ATILE;
        const __nv_bfloat16* sVh = adsm + (t & 1) * ABUF + 2 * ATILE;
        const __nv_bfloat16* sVl = adsm + (t & 1) * ABUF + 3 * ATILE;
        const int k0 = t * 64;

        if (k0 <= wlast) {
            float s[8][4];
#pragma unroll
            for (int nt = 0; nt < 8; nt++)
#pragma unroll
                for (int j = 0; j < 4; j++) s[nt][j] = 0.f;

#pragma unroll
            for (int nt = 0; nt < 8; nt++) {
                if (k0 + nt * 8 <= wlast) {
                    const int ko = (nt * 8 + r8) * AP + 8 * mi;
                    uint32_t bKh[8], bKl[8];
                    ldsm4(bKh,     sKh + ko);
                    ldsm4(bKh + 4, sKh + ko + 32);
                    ldsm4(bKl,     sKl + ko);
                    ldsm4(bKl + 4, sKl + ko + 32);
#pragma unroll
                    for (int ks = 0; ks < 4; ks++) {
                        mma16816(s[nt], aQh[ks], &bKh[2 * ks]);
                        mma16816(s[nt], aQh[ks], &bKl[2 * ks]);
                        mma16816(s[nt], aQl[ks], &bKh[2 * ks]);
                    }
                }
            }

            if (k0 + 63 > wr0) {
                const int row0 = wr0 + lr, row1 = wr0 + 8 + lr;
#pragma unroll
                for (int nt = 0; nt < 8; nt++) {
                    int kc = k0 + nt * 8 + 2 * lc;
                    if (kc > row0)     s[nt][0] = -1e30f;
                    if (kc + 1 > row0) s[nt][1] = -1e30f;
                    if (kc > row1)     s[nt][2] = -1e30f;
                    if (kc + 1 > row1) s[nt][3] = -1e30f;
                }
            }

            float tm0 = -1e30f, tm1 = -1e30f;
#pragma unroll
            for (int nt = 0; nt < 8; nt++) {
                tm0 = fmaxf(tm0, fmaxf(s[nt][0], s[nt][1]));
                tm1 = fmaxf(tm1, fmaxf(s[nt][2], s[nt][3]));
            }
            tm0 = fmaxf(tm0, __shfl_xor_sync(0xffffffff, tm0, 1));
            tm0 = fmaxf(tm0, __shfl_xor_sync(0xffffffff, tm0, 2));
            tm1 = fmaxf(tm1, __shfl_xor_sync(0xffffffff, tm1, 1));
            tm1 = fmaxf(tm1, __shfl_xor_sync(0xffffffff, tm1, 2));

            float mn0 = fmaxf(m0, tm0), mn1 = fmaxf(m1, tm1);
            float cr0 = fexp2((m0 - mn0) * L2E);
            float cr1 = fexp2((m1 - mn1) * L2E);
            m0 = mn0; m1 = mn1;
            const float nm0 = -m0 * L2E, nm1 = -m1 * L2E;

            float ls0 = 0.f, ls1 = 0.f;
#pragma unroll
            for (int nt = 0; nt < 8; nt++) {
                s[nt][0] = fexp2(fmaf(s[nt][0], L2E, nm0));
                s[nt][1] = fexp2(fmaf(s[nt][1], L2E, nm0));
                s[nt][2] = fexp2(fmaf(s[nt][2], L2E, nm1));
                s[nt][3] = fexp2(fmaf(s[nt][3], L2E, nm1));
                ls0 += s[nt][0] + s[nt][1];
                ls1 += s[nt][2] + s[nt][3];
            }
            ls0 += __shfl_xor_sync(0xffffffff, ls0, 1);
            ls0 += __shfl_xor_sync(0xffffffff, ls0, 2);
            ls1 += __shfl_xor_sync(0xffffffff, ls1, 1);
            ls1 += __shfl_xor_sync(0xffffffff, ls1, 2);
            l0 = l0 * cr0 + ls0;
            l1 = l1 * cr1 + ls1;
#pragma unroll
            for (int nt = 0; nt < 8; nt++) {
                o[nt][0] *= cr0; o[nt][1] *= cr0;
                o[nt][2] *= cr1; o[nt][3] *= cr1;
            }

            uint32_t pH[4][4], pL[4][4];
#pragma unroll
            for (int ks = 0; ks < 4; ks++) {
                if (k0 + ks * 16 <= wlast) {
                    split_pack(s[2*ks][0],   s[2*ks][1],   pH[ks][0], pL[ks][0]);
                    split_pack(s[2*ks][2],   s[2*ks][3],   pH[ks][1], pL[ks][1]);
                    split_pack(s[2*ks+1][0], s[2*ks+1][1], pH[ks][2], pL[ks][2]);
                    split_pack(s[2*ks+1][2], s[2*ks+1][3], pH[ks][3], pL[ks][3]);
                }
            }

#pragma unroll
            for (int dt = 0; dt < 8; dt++) {
                const int vo = lane * AP + dt * 8;   // key = lane row, d = 8*dt
                uint32_t bVh[8], bVl[8];
                ldsm4t(bVh,     sVh + vo);
                ldsm4t(bVh + 4, sVh + vo + 32 * AP);
                ldsm4t(bVl,     sVl + vo);
                ldsm4t(bVl + 4, sVl + vo + 32 * AP);
#pragma unroll
                for (int ks = 0; ks < 4; ks++) {
                    if (k0 + ks * 16 <= wlast) {
                        mma16816(o[dt], pH[ks], &bVh[2 * ks]);
                        mma16816(o[dt], pH[ks], &bVl[2 * ks]);
                        mma16816(o[dt], pL[ks], &bVh[2 * ks]);
                    }
                }
            }
        }
        __syncthreads();
    }

    const float i0 = 1.f / l0, i1 = 1.f / l1;
    const int b = bh >> 3;
    const int h = bh & 7;
    const int row0 = wr0 + lr, row1 = wr0 + 8 + lr;
    float* __restrict__ o0 = out + ((size_t)(b * SEQLEN + row0) * DOUT) + h * HDIM;
    float* __restrict__ o1 = out + ((size_t)(b * SEQLEN + row1) * DOUT) + h * HDIM;
#pragma unroll
    for (int nt = 0; nt < 8; nt++) {
        int d = nt * 8 + 2 * lc;
        *(float2*)&o0[d] = make_float2(o[nt][0] * i0, o[nt][1] * i0);
        *(float2*)&o1[d] = make_float2(o[nt][2] * i1, o[nt][3] * i1);
    }
}

// ---------------------------------------------------------------------------
extern "C" void kernel_launch(void* const* d_in, const int* in_sizes, int n_in,
                              void* d_out, int out_size)
{
    const float* Qs = (const float*)d_in[0];
    const float* Ks = (const float*)d_in[1];
    const float* Vs = (const float*)d_in[2];
    const float* WQ = (const float*)d_in[3];
    const float* WK = (const float*)d_in[4];
    const float* WV = (const float*)d_in[5];
    float* out = (float*)d_out;

    static bool attr_done = false;
    if (!attr_done) {
        cudaFuncSetAttribute(proj_mma_sync,
                             cudaFuncAttributeMaxDynamicSharedMemorySize, PROJ_DSMEM);
        cudaFuncSetAttribute(attn_mma,
                             cudaFuncAttributeMaxDynamicSharedMemorySize, ATTN_DSMEM);
        attr_done = true;
    }

    convert_x<<<dim3(MTOT * DIN / 8 / 256, 3), 256>>>(Qs, Ks, Vs);
    convert_wt<<<dim3(DOUT / 32, DIN / 32, 3), dim3(32, 8)>>>(WQ, WK, WV);
    proj_mma_sync<<<dim3(DOUT / 128, MTOT / 128, 3), 256, PROJ_DSMEM>>>();

    attn_mma<<<(SEQLEN / 128) * NBH, 256, ATTN_DSMEM>>>(out);
}

// round 10
// speedup vs baseline: 1.0960x; 1.0960x over previous
#include <cuda_runtime.h>
#include <cuda_bf16.h>
#include <cstdint>

#define BATCH 8
#define SEQLEN 1024
#define DIN 512
#define NHEAD 8
#define HDIM 64
#define DOUT 512
#define MTOT (BATCH * SEQLEN)   // 8192
#define NBH (BATCH * NHEAD)     // 64

// ---------------------------------------------------------------------------
// Static device scratch (no runtime allocation allowed)
// ---------------------------------------------------------------------------
__device__ __align__(16) __nv_bfloat16 g_xhi[3 * MTOT * DIN];
__device__ __align__(16) __nv_bfloat16 g_xlo[3 * MTOT * DIN];
__device__ __align__(16) __nv_bfloat16 g_wthi[3 * DOUT * DIN];
__device__ __align__(16) __nv_bfloat16 g_wtlo[3 * DOUT * DIN];

// projected q/k/v, head-major [bh][l][64], bf16 hi/lo
__device__ __align__(16) __nv_bfloat16 g_qhi[NBH * SEQLEN * HDIM];
__device__ __align__(16) __nv_bfloat16 g_qlo[NBH * SEQLEN * HDIM];
__device__ __align__(16) __nv_bfloat16 g_khi[NBH * SEQLEN * HDIM];
__device__ __align__(16) __nv_bfloat16 g_klo[NBH * SEQLEN * HDIM];
__device__ __align__(16) __nv_bfloat16 g_vhi[NBH * SEQLEN * HDIM];
__device__ __align__(16) __nv_bfloat16 g_vlo[NBH * SEQLEN * HDIM];

__device__ __forceinline__ void split_bf16(float x, __nv_bfloat16& h, __nv_bfloat16& l) {
    h = __float2bfloat16(x);
    l = __float2bfloat16(x - __bfloat162float(h));
}

__device__ __forceinline__ void mma16816(float* c, const uint32_t* a, const uint32_t* b) {
    asm volatile(
        "mma.sync.aligned.m16n8k16.row.col.f32.bf16.bf16.f32 "
        "{%0,%1,%2,%3}, {%4,%5,%6,%7}, {%8,%9}, {%0,%1,%2,%3};"
        : "+f"(c[0]), "+f"(c[1]), "+f"(c[2]), "+f"(c[3])
        : "r"(a[0]), "r"(a[1]), "r"(a[2]), "r"(a[3]), "r"(b[0]), "r"(b[1]));
}

__device__ __forceinline__ void ldsm4(uint32_t* r, const __nv_bfloat16* p) {
    uint32_t a = (uint32_t)__cvta_generic_to_shared(p);
    asm volatile("ldmatrix.sync.aligned.m8n8.x4.shared.b16 {%0,%1,%2,%3}, [%4];"
        : "=r"(r[0]), "=r"(r[1]), "=r"(r[2]), "=r"(r[3]) : "r"(a));
}
__device__ __forceinline__ void ldsm4t(uint32_t* r, const __nv_bfloat16* p) {
    uint32_t a = (uint32_t)__cvta_generic_to_shared(p);
    asm volatile("ldmatrix.sync.aligned.m8n8.x4.trans.shared.b16 {%0,%1,%2,%3}, [%4];"
        : "=r"(r[0]), "=r"(r[1]), "=r"(r[2]), "=r"(r[3]) : "r"(a));
}

// 16B global->shared async copy
__device__ __forceinline__ void cp16(void* smem_dst, const void* gsrc) {
    uint32_t sa = (uint32_t)__cvta_generic_to_shared(smem_dst);
    asm volatile("cp.async.cg.shared.global [%0], [%1], 16;" :: "r"(sa), "l"(gsrc));
}
#define CP_COMMIT() asm volatile("cp.async.commit_group;" ::: "memory")
#define CP_WAIT1()  asm volatile("cp.async.wait_group 1;" ::: "memory")
#define CP_WAIT0()  asm volatile("cp.async.wait_group 0;" ::: "memory")

// FMA-pipe exp2 (no MUFU), max rel err ~4e-5
__device__ __forceinline__ float fexp2(float t) {
    t = fmaxf(t, -126.0f);
    float z = t + 12582912.0f;
    int   i = __float_as_int(z) - 0x4B400000;
    float f = t - (z - 12582912.0f);
    float p = fmaf(f, 0.00961813f, 0.05550411f);
    p = fmaf(f, p, 0.24022651f);
    p = fmaf(f, p, 0.69314718f);
    p = fmaf(f, p, 1.0f);
    return p * __int_as_float((i + 127) << 23);
}
#define L2E 1.4426950408889634f

__device__ __forceinline__ void split_pack(float x, float y, uint32_t& hi, uint32_t& lo) {
    __nv_bfloat16 hx = __float2bfloat16(x), hy = __float2bfloat16(y);
    float rx = x - __bfloat162float(hx);
    float ry = y - __bfloat162float(hy);
    __nv_bfloat162 H(hx, hy);
    __nv_bfloat162 L(__float2bfloat16(rx), __float2bfloat16(ry));
    hi = *(uint32_t*)&H;
    lo = *(uint32_t*)&L;
}

// ---------------------------------------------------------------------------
// Conversion: X (fp32) -> bf16 hi/lo. 8 floats per thread, 16B stores.
// ---------------------------------------------------------------------------
__global__ __launch_bounds__(256) void convert_x(
    const float* __restrict__ x0, const float* __restrict__ x1,
    const float* __restrict__ x2)
{
    const int sel = blockIdx.y;
    const float* __restrict__ x = (sel == 0) ? x0 : (sel == 1) ? x1 : x2;
    const int i = blockIdx.x * 256 + threadIdx.x;
    const float4* xv = (const float4*)x;
    float4 a = xv[2 * i], b = xv[2 * i + 1];

    uint32_t h01, h23, h45, h67, l01, l23, l45, l67;
    split_pack(a.x, a.y, h01, l01);
    split_pack(a.z, a.w, h23, l23);
    split_pack(b.x, b.y, h45, l45);
    split_pack(b.z, b.w, h67, l67);

    const size_t e = (size_t)sel * (MTOT * DIN) + (size_t)i * 8;
    *(uint4*)&g_xhi[e] = make_uint4(h01, h23, h45, h67);
    *(uint4*)&g_xlo[e] = make_uint4(l01, l23, l45, l67);
}

__global__ __launch_bounds__(256) void convert_wt(
    const float* __restrict__ w0, const float* __restrict__ w1,
    const float* __restrict__ w2)
{
    const int sel = blockIdx.z;
    const float* __restrict__ W = (sel == 0) ? w0 : (sel == 1) ? w1 : w2;
    __shared__ float tile[32][33];
    const int n0 = blockIdx.x * 32, k0 = blockIdx.y * 32;
    const int tx = threadIdx.x, ty = threadIdx.y;
#pragma unroll
    for (int i = 0; i < 32; i += 8)
        tile[ty + i][tx] = W[(k0 + ty + i) * DOUT + n0 + tx];
    __syncthreads();
    const size_t base = (size_t)sel * (DOUT * DIN);
#pragma unroll
    for (int i = 0; i < 32; i += 8) {
        int n = ty + i;
        float v = tile[tx][n];
        __nv_bfloat16 h, l;
        split_bf16(v, h, l);
        g_wthi[base + (size_t)(n0 + n) * DIN + k0 + tx] = h;
        g_wtlo[base + (size_t)(n0 + n) * DIN + k0 + tx] = l;
    }
}

// ---------------------------------------------------------------------------
// Projection GEMM, bf16-split mma.sync, cp.async double buffer, ldmatrix frags.
// ---------------------------------------------------------------------------
#define PADK 40
#define PTILE (128 * PADK)
#define PBUF  (4 * PTILE)
#define PROJ_DSMEM (2 * PBUF * 2)

__global__ __launch_bounds__(256) void proj_mma_sync()
{
    extern __shared__ __align__(16) __nv_bfloat16 dsm[];

    const int sel = blockIdx.z;
    const int n0  = blockIdx.x * 128;
    const int m0  = blockIdx.y * 128;
    const int tid = threadIdx.x;
    const int w   = tid >> 5;
    const int lane = tid & 31;
    const int wm = w >> 2, wn = w & 3;
    const int lr = lane >> 2, lc = lane & 3;
    const int mi = lane >> 3, r8 = lane & 7;

    const __nv_bfloat16* __restrict__ Ahp = g_xhi + (size_t)sel * (MTOT * DIN);
    const __nv_bfloat16* __restrict__ Alp = g_xlo + (size_t)sel * (MTOT * DIN);
    const __nv_bfloat16* __restrict__ Bhp = g_wthi + (size_t)sel * (DOUT * DIN);
    const __nv_bfloat16* __restrict__ Blp = g_wtlo + (size_t)sel * (DOUT * DIN);

    const int r0 = tid >> 2, c0 = (tid & 3) * 8;
    const int r1 = (tid + 256) >> 2, c1 = ((tid + 256) & 3) * 8;

    auto issue = [&](int slab, int buf) {
        const int kk = slab * 32;
        __nv_bfloat16* base = dsm + buf * PBUF;
        const size_t ga0 = (size_t)(m0 + r0) * DIN + kk + c0;
        const size_t gb0 = (size_t)(n0 + r0) * DIN + kk + c0;
        const size_t ga1 = (size_t)(m0 + r1) * DIN + kk + c1;
        const size_t gb1 = (size_t)(n0 + r1) * DIN + kk + c1;
        cp16(base + 0 * PTILE + r0 * PADK + c0, Ahp + ga0);
        cp16(base + 1 * PTILE + r0 * PADK + c0, Alp + ga0);
        cp16(base + 2 * PTILE + r0 * PADK + c0, Bhp + gb0);
        cp16(base + 3 * PTILE + r0 * PADK + c0, Blp + gb0);
        cp16(base + 0 * PTILE + r1 * PADK + c1, Ahp + ga1);
        cp16(base + 1 * PTILE + r1 * PADK + c1, Alp + ga1);
        cp16(base + 2 * PTILE + r1 * PADK + c1, Bhp + gb1);
        cp16(base + 3 * PTILE + r1 * PADK + c1, Blp + gb1);
        CP_COMMIT();
    };

    const int bofs = (wn * 32 + r8) * PADK + 8 * mi;
    const int aofs = (wm * 64 + (mi & 1) * 8 + r8) * PADK + (mi >> 1) * 8;

    float acc[4][4][4];
#pragma unroll
    for (int i = 0; i < 4; i++)
#pragma unroll
        for (int j = 0; j < 4; j++)
#pragma unroll
            for (int r = 0; r < 4; r++) acc[i][j][r] = 0.f;

    issue(0, 0);

    for (int s = 0; s < DIN / 32; s++) {
        if (s + 1 < DIN / 32) { issue(s + 1, (s + 1) & 1); CP_WAIT1(); }
        else                  { CP_WAIT0(); }
        __syncthreads();

        const __nv_bfloat16* sAh = dsm + (s & 1) * PBUF + 0 * PTILE;
        const __nv_bfloat16* sAl = dsm + (s & 1) * PBUF + 1 * PTILE;
        const __nv_bfloat16* sBh = dsm + (s & 1) * PBUF + 2 * PTILE;
        const __nv_bfloat16* sBl = dsm + (s & 1) * PBUF + 3 * PTILE;

        uint32_t bH[4][4], bL[4][4];
#pragma unroll
        for (int nt = 0; nt < 4; nt++) {
            ldsm4(bH[nt], sBh + bofs + nt * 8 * PADK);
            ldsm4(bL[nt], sBl + bofs + nt * 8 * PADK);
        }

#pragma unroll
        for (int ks = 0; ks < 2; ks++) {
            uint32_t af[4][4];
#pragma unroll
            for (int mt = 0; mt < 4; mt++)
                ldsm4(af[mt], sAh + aofs + mt * 16 * PADK + ks * 16);
#pragma unroll
            for (int mt = 0; mt < 4; mt++)
#pragma unroll
                for (int nt = 0; nt < 4; nt++) {
                    mma16816(acc[mt][nt], af[mt], &bH[nt][2 * ks]);
                    mma16816(acc[mt][nt], af[mt], &bL[nt][2 * ks]);
                }
#pragma unroll
            for (int mt = 0; mt < 4; mt++)
                ldsm4(af[mt], sAl + aofs + mt * 16 * PADK + ks * 16);
#pragma unroll
            for (int mt = 0; mt < 4; mt++)
#pragma unroll
                for (int nt = 0; nt < 4; nt++)
                    mma16816(acc[mt][nt], af[mt], &bH[nt][2 * ks]);
        }
        __syncthreads();
    }

    const float scale = (sel == 0) ? 0.125f : 1.0f;
    __nv_bfloat16* __restrict__ dh = (sel == 0) ? g_qhi : (sel == 1) ? g_khi : g_vhi;
    __nv_bfloat16* __restrict__ dl = (sel == 0) ? g_qlo : (sel == 1) ? g_klo : g_vlo;
#pragma unroll
    for (int mt = 0; mt < 4; mt++) {
#pragma unroll
        for (int half = 0; half < 2; half++) {
            int m = m0 + wm * 64 + mt * 16 + half * 8 + lr;
            int b = m >> 10;
            int l = m & 1023;
#pragma unroll
            for (int nt = 0; nt < 4; nt++) {
                int n = n0 + wn * 32 + nt * 8 + lc * 2;
                int h = n >> 6;
                int d = n & 63;
                uint32_t hi, lo;
                split_pack(acc[mt][nt][half * 2 + 0] * scale,
                           acc[mt][nt][half * 2 + 1] * scale, hi, lo);
                size_t off = (((size_t)(b * NHEAD + h) * SEQLEN) + l) * HDIM + d;
                *(uint32_t*)&dh[off] = hi;
                *(uint32_t*)&dl[off] = lo;
            }
        }
    }
}

// ---------------------------------------------------------------------------
// Flash attention: 128-thread CTAs (64 q rows, 4 warps), 3 CTAs/SM.
// K and V both [key][d] row-major in smem; V transposed via ldmatrix.trans.
// ---------------------------------------------------------------------------
#define AP 72
#define ATILE (64 * AP)
#define ABUF  (4 * ATILE)
#define ATTN_DSMEM (2 * ABUF * 2)
#define QBLK 64

__global__ __launch_bounds__(128, 3) void attn_mma(float* __restrict__ out)
{
    extern __shared__ __align__(16) __nv_bfloat16 adsm[];

    // longest-first schedule over 16 q-blocks x 64 bh
    const int bh  = blockIdx.x & (NBH - 1);
    const int qb  = (SEQLEN / QBLK - 1) - (blockIdx.x >> 6);
    const int q0  = qb * QBLK;
    const int tid = threadIdx.x;
    const int w    = tid >> 5;            // 0..3
    const int lane = tid & 31;
    const int lr = lane >> 2, lc = lane & 3;
    const int mi = lane >> 3, r8 = lane & 7;
    const int wr0 = q0 + w * 16;
    const int wlast = wr0 + 15;

    const size_t bhoff = (size_t)bh * (SEQLEN * HDIM);
    const __nv_bfloat16* __restrict__ Kh = g_khi + bhoff;
    const __nv_bfloat16* __restrict__ Kl = g_klo + bhoff;
    const __nv_bfloat16* __restrict__ Vh = g_vhi + bhoff;
    const __nv_bfloat16* __restrict__ Vl = g_vlo + bhoff;

    auto issue = [&](int tileidx, int buf) {
        const int k0 = tileidx * 64;
        __nv_bfloat16* base = adsm + buf * ABUF;
#pragma unroll
        for (int i = 0; i < 4; i++) {
            int idx = tid + i * 128;          // 0..511
            int r = idx >> 3;                 // 0..63
            int c = (idx & 7) * 8;
            const size_t g = (size_t)(k0 + r) * HDIM + c;
            const int sm = r * AP + c;
            cp16(base + 0 * ATILE + sm, Kh + g);
            cp16(base + 1 * ATILE + sm, Kl + g);
            cp16(base + 2 * ATILE + sm, Vh + g);
            cp16(base + 3 * ATILE + sm, Vl + g);
        }
        CP_COMMIT();
    };

    uint32_t aQh[4][4], aQl[4][4];
    {
        const __nv_bfloat16* __restrict__ Qh = g_qhi + bhoff;
        const __nv_bfloat16* __restrict__ Ql = g_qlo + bhoff;
#pragma unroll
        for (int ks = 0; ks < 4; ks++) {
            int k = ks * 16 + 2 * lc;
            aQh[ks][0] = *(const uint32_t*)&Qh[(wr0 + lr) * HDIM + k];
            aQh[ks][1] = *(const uint32_t*)&Qh[(wr0 + 8 + lr) * HDIM + k];
            aQh[ks][2] = *(const uint32_t*)&Qh[(wr0 + lr) * HDIM + k + 8];
            aQh[ks][3] = *(const uint32_t*)&Qh[(wr0 + 8 + lr) * HDIM + k + 8];
            aQl[ks][0] = *(const uint32_t*)&Ql[(wr0 + lr) * HDIM + k];
            aQl[ks][1] = *(const uint32_t*)&Ql[(wr0 + 8 + lr) * HDIM + k];
            aQl[ks][2] = *(const uint32_t*)&Ql[(wr0 + lr) * HDIM + k + 8];
            aQl[ks][3] = *(const uint32_t*)&Ql[(wr0 + 8 + lr) * HDIM + k + 8];
        }
    }

    float o[8][4];
#pragma unroll
    for (int nt = 0; nt < 8; nt++)
#pragma unroll
        for (int j = 0; j < 4; j++) o[nt][j] = 0.f;
    float m0 = -1e30f, m1 = -1e30f, l0 = 0.f, l1 = 0.f;

    const int ntiles = qb + 1;
    issue(0, 0);

    for (int t = 0; t < ntiles; t++) {
        if (t + 1 < ntiles) { issue(t + 1, (t + 1) & 1); CP_WAIT1(); }
        else                { CP_WAIT0(); }
        __syncthreads();

        const __nv_bfloat16* sKh = adsm + (t & 1) * ABUF + 0 * ATILE;
        const __nv_bfloat16* sKl = adsm + (t & 1) * ABUF + 1 * ATILE;
        const __nv_bfloat16* sVh = adsm + (t & 1) * ABUF + 2 * ATILE;
        const __nv_bfloat16* sVl = adsm + (t & 1) * ABUF + 3 * ATILE;
        const int k0 = t * 64;

        {
            float s[8][4];
#pragma unroll
            for (int nt = 0; nt < 8; nt++)
#pragma unroll
                for (int j = 0; j < 4; j++) s[nt][j] = 0.f;

#pragma unroll
            for (int nt = 0; nt < 8; nt++) {
                if (k0 + nt * 8 <= wlast) {
                    const int ko = (nt * 8 + r8) * AP + 8 * mi;
                    uint32_t bKh[8], bKl[8];
                    ldsm4(bKh,     sKh + ko);
                    ldsm4(bKh + 4, sKh + ko + 32);
                    ldsm4(bKl,     sKl + ko);
                    ldsm4(bKl + 4, sKl + ko + 32);
#pragma unroll
                    for (int ks = 0; ks < 4; ks++) {
                        mma16816(s[nt], aQh[ks], &bKh[2 * ks]);
                        mma16816(s[nt], aQh[ks], &bKl[2 * ks]);
                        mma16816(s[nt], aQl[ks], &bKh[2 * ks]);
                    }
                }
            }

            if (k0 + 63 > wr0) {
                const int row0 = wr0 + lr, row1 = wr0 + 8 + lr;
#pragma unroll
                for (int nt = 0; nt < 8; nt++) {
                    int kc = k0 + nt * 8 + 2 * lc;
                    if (kc > row0)     s[nt][0] = -1e30f;
                    if (kc + 1 > row0) s[nt][1] = -1e30f;
                    if (kc > row1)     s[nt][2] = -1e30f;
                    if (kc + 1 > row1) s[nt][3] = -1e30f;
                }
            }

            float tm0 = -1e30f, tm1 = -1e30f;
#pragma unroll
            for (int nt = 0; nt < 8; nt++) {
                tm0 = fmaxf(tm0, fmaxf(s[nt][0], s[nt][1]));
                tm1 = fmaxf(tm1, fmaxf(s[nt][2], s[nt][3]));
            }
            tm0 = fmaxf(tm0, __shfl_xor_sync(0xffffffff, tm0, 1));
            tm0 = fmaxf(tm0, __shfl_xor_sync(0xffffffff, tm0, 2));
            tm1 = fmaxf(tm1, __shfl_xor_sync(0xffffffff, tm1, 1));
            tm1 = fmaxf(tm1, __shfl_xor_sync(0xffffffff, tm1, 2));

            float mn0 = fmaxf(m0, tm0), mn1 = fmaxf(m1, tm1);
            float cr0 = fexp2((m0 - mn0) * L2E);
            float cr1 = fexp2((m1 - mn1) * L2E);
            m0 = mn0; m1 = mn1;
            const float nm0 = -m0 * L2E, nm1 = -m1 * L2E;

            float ls0 = 0.f, ls1 = 0.f;
#pragma unroll
            for (int nt = 0; nt < 8; nt++) {
                s[nt][0] = fexp2(fmaf(s[nt][0], L2E, nm0));
                s[nt][1] = fexp2(fmaf(s[nt][1], L2E, nm0));
                s[nt][2] = fexp2(fmaf(s[nt][2], L2E, nm1));
                s[nt][3] = fexp2(fmaf(s[nt][3], L2E, nm1));
                ls0 += s[nt][0] + s[nt][1];
                ls1 += s[nt][2] + s[nt][3];
            }
            ls0 += __shfl_xor_sync(0xffffffff, ls0, 1);
            ls0 += __shfl_xor_sync(0xffffffff, ls0, 2);
            ls1 += __shfl_xor_sync(0xffffffff, ls1, 1);
            ls1 += __shfl_xor_sync(0xffffffff, ls1, 2);
            l0 = l0 * cr0 + ls0;
            l1 = l1 * cr1 + ls1;
#pragma unroll
            for (int nt = 0; nt < 8; nt++) {
                o[nt][0] *= cr0; o[nt][1] *= cr0;
                o[nt][2] *= cr1; o[nt][3] *= cr1;
            }

            uint32_t pH[4][4], pL[4][4];
#pragma unroll
            for (int ks = 0; ks < 4; ks++) {
                if (k0 + ks * 16 <= wlast) {
                    split_pack(s[2*ks][0],   s[2*ks][1],   pH[ks][0], pL[ks][0]);
                    split_pack(s[2*ks][2],   s[2*ks][3],   pH[ks][1], pL[ks][1]);
                    split_pack(s[2*ks+1][0], s[2*ks+1][1], pH[ks][2], pL[ks][2]);
                    split_pack(s[2*ks+1][2], s[2*ks+1][3], pH[ks][3], pL[ks][3]);
                }
            }

#pragma unroll
            for (int dt = 0; dt < 8; dt++) {
                const int vo = lane * AP + dt * 8;
                uint32_t bVh[8], bVl[8];
                ldsm4t(bVh,     sVh + vo);
                ldsm4t(bVh + 4, sVh + vo + 32 * AP);
                ldsm4t(bVl,     sVl + vo);
                ldsm4t(bVl + 4, sVl + vo + 32 * AP);
#pragma unroll
                for (int ks = 0; ks < 4; ks++) {
                    if (k0 + ks * 16 <= wlast) {
                        mma16816(o[dt], pH[ks], &bVh[2 * ks]);
                        mma16816(o[dt], pH[ks], &bVl[2 * ks]);
                        mma16816(o[dt], pL[ks], &bVh[2 * ks]);
                    }
                }
            }
        }
        __syncthreads();
    }

    const float i0 = 1.f / l0, i1 = 1.f / l1;
    const int b = bh >> 3;
    const int h = bh & 7;
    const int row0 = wr0 + lr, row1 = wr0 + 8 + lr;
    float* __restrict__ o0 = out + ((size_t)(b * SEQLEN + row0) * DOUT) + h * HDIM;
    float* __restrict__ o1 = out + ((size_t)(b * SEQLEN + row1) * DOUT) + h * HDIM;
#pragma unroll
    for (int nt = 0; nt < 8; nt++) {
        int d = nt * 8 + 2 * lc;
        *(float2*)&o0[d] = make_float2(o[nt][0] * i0, o[nt][1] * i0);
        *(float2*)&o1[d] = make_float2(o[nt][2] * i1, o[nt][3] * i1);
    }
}

// ---------------------------------------------------------------------------
extern "C" void kernel_launch(void* const* d_in, const int* in_sizes, int n_in,
                              void* d_out, int out_size)
{
    const float* Qs = (const float*)d_in[0];
    const float* Ks = (const float*)d_in[1];
    const float* Vs = (const float*)d_in[2];
    const float* WQ = (const float*)d_in[3];
    const float* WK = (const float*)d_in[4];
    const float* WV = (const float*)d_in[5];
    float* out = (float*)d_out;

    static bool attr_done = false;
    if (!attr_done) {
        cudaFuncSetAttribute(proj_mma_sync,
                             cudaFuncAttributeMaxDynamicSharedMemorySize, PROJ_DSMEM);
        cudaFuncSetAttribute(attn_mma,
                             cudaFuncAttributeMaxDynamicSharedMemorySize, ATTN_DSMEM);
        attr_done = true;
    }

    convert_x<<<dim3(MTOT * DIN / 8 / 256, 3), 256>>>(Qs, Ks, Vs);
    convert_wt<<<dim3(DOUT / 32, DIN / 32, 3), dim3(32, 8)>>>(WQ, WK, WV);
    proj_mma_sync<<<dim3(DOUT / 128, MTOT / 128, 3), 256, PROJ_DSMEM>>>();

    attn_mma<<<(SEQLEN / QBLK) * NBH, 128, ATTN_DSMEM>>>(out);
}

// round 11
// speedup vs baseline: 1.7063x; 1.5568x over previous
#include <cuda_runtime.h>
#include <cuda_fp16.h>
#include <cstdint>

#define BATCH 8
#define SEQLEN 1024
#define DIN 512
#define NHEAD 8
#define HDIM 64
#define DOUT 512
#define MTOT (BATCH * SEQLEN)   // 8192
#define NBH (BATCH * NHEAD)     // 64

// ---------------------------------------------------------------------------
// Static device scratch (no runtime allocation allowed)
// ---------------------------------------------------------------------------
__device__ __align__(16) __half g_xhi[3 * MTOT * DIN];
__device__ __align__(16) __half g_xlo[3 * MTOT * DIN];
__device__ __align__(16) __half g_wthi[3 * DOUT * DIN];

// projected q/k/v, head-major [bh][l][64]; q split hi/lo, k/v hi only
__device__ __align__(16) __half g_qhi[NBH * SEQLEN * HDIM];
__device__ __align__(16) __half g_qlo[NBH * SEQLEN * HDIM];
__device__ __align__(16) __half g_khi[NBH * SEQLEN * HDIM];
__device__ __align__(16) __half g_vhi[NBH * SEQLEN * HDIM];

__device__ __forceinline__ void mma16816(float* c, const uint32_t* a, const uint32_t* b) {
    asm volatile(
        "mma.sync.aligned.m16n8k16.row.col.f32.f16.f16.f32 "
        "{%0,%1,%2,%3}, {%4,%5,%6,%7}, {%8,%9}, {%0,%1,%2,%3};"
        : "+f"(c[0]), "+f"(c[1]), "+f"(c[2]), "+f"(c[3])
        : "r"(a[0]), "r"(a[1]), "r"(a[2]), "r"(a[3]), "r"(b[0]), "r"(b[1]));
}

__device__ __forceinline__ void ldsm4(uint32_t* r, const __half* p) {
    uint32_t a = (uint32_t)__cvta_generic_to_shared(p);
    asm volatile("ldmatrix.sync.aligned.m8n8.x4.shared.b16 {%0,%1,%2,%3}, [%4];"
        : "=r"(r[0]), "=r"(r[1]), "=r"(r[2]), "=r"(r[3]) : "r"(a));
}
__device__ __forceinline__ void ldsm4t(uint32_t* r, const __half* p) {
    uint32_t a = (uint32_t)__cvta_generic_to_shared(p);
    asm volatile("ldmatrix.sync.aligned.m8n8.x4.trans.shared.b16 {%0,%1,%2,%3}, [%4];"
        : "=r"(r[0]), "=r"(r[1]), "=r"(r[2]), "=r"(r[3]) : "r"(a));
}

// 16B global->shared async copy
__device__ __forceinline__ void cp16(void* smem_dst, const void* gsrc) {
    uint32_t sa = (uint32_t)__cvta_generic_to_shared(smem_dst);
    asm volatile("cp.async.cg.shared.global [%0], [%1], 16;" :: "r"(sa), "l"(gsrc));
}
#define CP_COMMIT() asm volatile("cp.async.commit_group;" ::: "memory")
#define CP_WAIT1()  asm volatile("cp.async.wait_group 1;" ::: "memory")
#define CP_WAIT0()  asm volatile("cp.async.wait_group 0;" ::: "memory")

// FMA-pipe exp2 (no MUFU), max rel err ~4e-5
__device__ __forceinline__ float fexp2(float t) {
    t = fmaxf(t, -126.0f);
    float z = t + 12582912.0f;
    int   i = __float_as_int(z) - 0x4B400000;
    float f = t - (z - 12582912.0f);
    float p = fmaf(f, 0.00961813f, 0.05550411f);
    p = fmaf(f, p, 0.24022651f);
    p = fmaf(f, p, 0.69314718f);
    p = fmaf(f, p, 1.0f);
    return p * __int_as_float((i + 127) << 23);
}
#define L2E 1.4426950408889634f

// fp16 split: hi = rn(x), lo = rn(x - hi); pack pairs into b32 frags
__device__ __forceinline__ void split_pack_h(float x, float y, uint32_t& hi, uint32_t& lo) {
    __half hx = __float2half_rn(x), hy = __float2half_rn(y);
    float rx = x - __half2float(hx);
    float ry = y - __half2float(hy);
    __half2 H = __halves2half2(hx, hy);
    __half2 L = __halves2half2(__float2half_rn(rx), __float2half_rn(ry));
    hi = *(uint32_t*)&H;
    lo = *(uint32_t*)&L;
}
__device__ __forceinline__ uint32_t round_pack_h(float x, float y) {
    __half2 H = __halves2half2(__float2half_rn(x), __float2half_rn(y));
    return *(uint32_t*)&H;
}

// ---------------------------------------------------------------------------
// Conversion: X (fp32) -> fp16 hi/lo. 8 floats per thread, 16B stores.
// ---------------------------------------------------------------------------
__global__ __launch_bounds__(256) void convert_x(
    const float* __restrict__ x0, const float* __restrict__ x1,
    const float* __restrict__ x2)
{
    const int sel = blockIdx.y;
    const float* __restrict__ x = (sel == 0) ? x0 : (sel == 1) ? x1 : x2;
    const int i = blockIdx.x * 256 + threadIdx.x;
    const float4* xv = (const float4*)x;
    float4 a = xv[2 * i], b = xv[2 * i + 1];

    uint32_t h01, h23, h45, h67, l01, l23, l45, l67;
    split_pack_h(a.x, a.y, h01, l01);
    split_pack_h(a.z, a.w, h23, l23);
    split_pack_h(b.x, b.y, h45, l45);
    split_pack_h(b.z, b.w, h67, l67);

    const size_t e = (size_t)sel * (MTOT * DIN) + (size_t)i * 8;
    *(uint4*)&g_xhi[e] = make_uint4(h01, h23, h45, h67);
    *(uint4*)&g_xlo[e] = make_uint4(l01, l23, l45, l67);
}

// W [k][n] fp32 -> transposed fp16 (rounded) [n][k]
__global__ __launch_bounds__(256) void convert_wt(
    const float* __restrict__ w0, const float* __restrict__ w1,
    const float* __restrict__ w2)
{
    const int sel = blockIdx.z;
    const float* __restrict__ W = (sel == 0) ? w0 : (sel == 1) ? w1 : w2;
    __shared__ float tile[32][33];
    const int n0 = blockIdx.x * 32, k0 = blockIdx.y * 32;
    const int tx = threadIdx.x, ty = threadIdx.y;
#pragma unroll
    for (int i = 0; i < 32; i += 8)
        tile[ty + i][tx] = W[(k0 + ty + i) * DOUT + n0 + tx];
    __syncthreads();
    const size_t base = (size_t)sel * (DOUT * DIN);
#pragma unroll
    for (int i = 0; i < 32; i += 8) {
        int n = ty + i;
        g_wthi[base + (size_t)(n0 + n) * DIN + k0 + tx] = __float2half_rn(tile[tx][n]);
    }
}

// ---------------------------------------------------------------------------
// Projection GEMM: fp16-split 2-pass mma.sync, cp.async double buffer.
// C = (Ah + Al) * Bh  (B rounded to fp16; error ~2^-11 rel)
// ---------------------------------------------------------------------------
#define PADK 40
#define PTILE (128 * PADK)
#define PBUF  (3 * PTILE)
#define PROJ_DSMEM (2 * PBUF * 2)

__global__ __launch_bounds__(256) void proj_mma_sync()
{
    extern __shared__ __align__(16) __half dsm[];

    const int sel = blockIdx.z;
    const int n0  = blockIdx.x * 128;
    const int m0  = blockIdx.y * 128;
    const int tid = threadIdx.x;
    const int w   = tid >> 5;
    const int lane = tid & 31;
    const int wm = w >> 2, wn = w & 3;
    const int lr = lane >> 2, lc = lane & 3;
    const int mi = lane >> 3, r8 = lane & 7;

    const __half* __restrict__ Ahp = g_xhi + (size_t)sel * (MTOT * DIN);
    const __half* __restrict__ Alp = g_xlo + (size_t)sel * (MTOT * DIN);
    const __half* __restrict__ Bhp = g_wthi + (size_t)sel * (DOUT * DIN);

    const int r0 = tid >> 2, c0 = (tid & 3) * 8;
    const int r1 = (tid + 256) >> 2, c1 = ((tid + 256) & 3) * 8;

    auto issue = [&](int slab, int buf) {
        const int kk = slab * 32;
        __half* base = dsm + buf * PBUF;
        const size_t ga0 = (size_t)(m0 + r0) * DIN + kk + c0;
        const size_t gb0 = (size_t)(n0 + r0) * DIN + kk + c0;
        const size_t ga1 = (size_t)(m0 + r1) * DIN + kk + c1;
        const size_t gb1 = (size_t)(n0 + r1) * DIN + kk + c1;
        cp16(base + 0 * PTILE + r0 * PADK + c0, Ahp + ga0);
        cp16(base + 1 * PTILE + r0 * PADK + c0, Alp + ga0);
        cp16(base + 2 * PTILE + r0 * PADK + c0, Bhp + gb0);
        cp16(base + 0 * PTILE + r1 * PADK + c1, Ahp + ga1);
        cp16(base + 1 * PTILE + r1 * PADK + c1, Alp + ga1);
        cp16(base + 2 * PTILE + r1 * PADK + c1, Bhp + gb1);
        CP_COMMIT();
    };

    const int bofs = (wn * 32 + r8) * PADK + 8 * mi;
    const int aofs = (wm * 64 + (mi & 1) * 8 + r8) * PADK + (mi >> 1) * 8;

    float acc[4][4][4];
#pragma unroll
    for (int i = 0; i < 4; i++)
#pragma unroll
        for (int j = 0; j < 4; j++)
#pragma unroll
            for (int r = 0; r < 4; r++) acc[i][j][r] = 0.f;

    issue(0, 0);

    for (int s = 0; s < DIN / 32; s++) {
        if (s + 1 < DIN / 32) { issue(s + 1, (s + 1) & 1); CP_WAIT1(); }
        else                  { CP_WAIT0(); }
        __syncthreads();

        const __half* sAh = dsm + (s & 1) * PBUF + 0 * PTILE;
        const __half* sAl = dsm + (s & 1) * PBUF + 1 * PTILE;
        const __half* sBh = dsm + (s & 1) * PBUF + 2 * PTILE;

        uint32_t bH[4][4];
#pragma unroll
        for (int nt = 0; nt < 4; nt++)
            ldsm4(bH[nt], sBh + bofs + nt * 8 * PADK);

#pragma unroll
        for (int ks = 0; ks < 2; ks++) {
            uint32_t af[4][4];
#pragma unroll
            for (int mt = 0; mt < 4; mt++)
                ldsm4(af[mt], sAh + aofs + mt * 16 * PADK + ks * 16);
#pragma unroll
            for (int mt = 0; mt < 4; mt++)
#pragma unroll
                for (int nt = 0; nt < 4; nt++)
                    mma16816(acc[mt][nt], af[mt], &bH[nt][2 * ks]);
#pragma unroll
            for (int mt = 0; mt < 4; mt++)
                ldsm4(af[mt], sAl + aofs + mt * 16 * PADK + ks * 16);
#pragma unroll
            for (int mt = 0; mt < 4; mt++)
#pragma unroll
                for (int nt = 0; nt < 4; nt++)
                    mma16816(acc[mt][nt], af[mt], &bH[nt][2 * ks]);
        }
        __syncthreads();
    }

    // ---- epilogue: q split hi/lo; k,v rounded hi only ----
#pragma unroll
    for (int mt = 0; mt < 4; mt++) {
#pragma unroll
        for (int half = 0; half < 2; half++) {
            int m = m0 + wm * 64 + mt * 16 + half * 8 + lr;
            int b = m >> 10;
            int l = m & 1023;
#pragma unroll
            for (int nt = 0; nt < 4; nt++) {
                int n = n0 + wn * 32 + nt * 8 + lc * 2;
                int h = n >> 6;
                int d = n & 63;
                size_t off = (((size_t)(b * NHEAD + h) * SEQLEN) + l) * HDIM + d;
                float v0 = acc[mt][nt][half * 2 + 0];
                float v1 = acc[mt][nt][half * 2 + 1];
                if (sel == 0) {
                    uint32_t hi, lo;
                    split_pack_h(v0 * 0.125f, v1 * 0.125f, hi, lo);
                    *(uint32_t*)&g_qhi[off] = hi;
                    *(uint32_t*)&g_qlo[off] = lo;
                } else {
                    __half* dst = (sel == 1) ? g_khi : g_vhi;
                    *(uint32_t*)&dst[off] = round_pack_h(v0, v1);
                }
            }
        }
    }
}

// ---------------------------------------------------------------------------
// Flash attention: fp16-split 2-pass. S = (Qh+Ql)*Kh; O += (Ph+Pl)*Vh.
// 128-thread CTAs (64 q rows), 3 CTAs/SM; only Kh, Vh tiles in smem.
// ---------------------------------------------------------------------------
#define AP 72
#define ATILE (64 * AP)
#define ABUF  (2 * ATILE)
#define ATTN_DSMEM (2 * ABUF * 2)
#define QBLK 64

__global__ __launch_bounds__(128, 3) void attn_mma(float* __restrict__ out)
{
    extern __shared__ __align__(16) __half adsm[];

    const int bh  = blockIdx.x & (NBH - 1);
    const int qb  = (SEQLEN / QBLK - 1) - (blockIdx.x >> 6);
    const int q0  = qb * QBLK;
    const int tid = threadIdx.x;
    const int w    = tid >> 5;
    const int lane = tid & 31;
    const int lr = lane >> 2, lc = lane & 3;
    const int mi = lane >> 3, r8 = lane & 7;
    const int wr0 = q0 + w * 16;
    const int wlast = wr0 + 15;

    const size_t bhoff = (size_t)bh * (SEQLEN * HDIM);
    const __half* __restrict__ Kh = g_khi + bhoff;
    const __half* __restrict__ Vh = g_vhi + bhoff;

    auto issue = [&](int tileidx, int buf) {
        const int k0 = tileidx * 64;
        __half* base = adsm + buf * ABUF;
#pragma unroll
        for (int i = 0; i < 4; i++) {
            int idx = tid + i * 128;          // 0..511
            int r = idx >> 3;
            int c = (idx & 7) * 8;
            const size_t g = (size_t)(k0 + r) * HDIM + c;
            const int sm = r * AP + c;
            cp16(base + 0 * ATILE + sm, Kh + g);
            cp16(base + 1 * ATILE + sm, Vh + g);
        }
        CP_COMMIT();
    };

    uint32_t aQh[4][4], aQl[4][4];
    {
        const __half* __restrict__ Qh = g_qhi + bhoff;
        const __half* __restrict__ Ql = g_qlo + bhoff;
#pragma unroll
        for (int ks = 0; ks < 4; ks++) {
            int k = ks * 16 + 2 * lc;
            aQh[ks][0] = *(const uint32_t*)&Qh[(wr0 + lr) * HDIM + k];
            aQh[ks][1] = *(const uint32_t*)&Qh[(wr0 + 8 + lr) * HDIM + k];
            aQh[ks][2] = *(const uint32_t*)&Qh[(wr0 + lr) * HDIM + k + 8];
            aQh[ks][3] = *(const uint32_t*)&Qh[(wr0 + 8 + lr) * HDIM + k + 8];
            aQl[ks][0] = *(const uint32_t*)&Ql[(wr0 + lr) * HDIM + k];
            aQl[ks][1] = *(const uint32_t*)&Ql[(wr0 + 8 + lr) * HDIM + k];
            aQl[ks][2] = *(const uint32_t*)&Ql[(wr0 + lr) * HDIM + k + 8];
            aQl[ks][3] = *(const uint32_t*)&Ql[(wr0 + 8 + lr) * HDIM + k + 8];
        }
    }

    float o[8][4];
#pragma unroll
    for (int nt = 0; nt < 8; nt++)
#pragma unroll
        for (int j = 0; j < 4; j++) o[nt][j] = 0.f;
    float m0 = -1e30f, m1 = -1e30f, l0 = 0.f, l1 = 0.f;

    const int ntiles = qb + 1;
    issue(0, 0);

    for (int t = 0; t < ntiles; t++) {
        if (t + 1 < ntiles) { issue(t + 1, (t + 1) & 1); CP_WAIT1(); }
        else                { CP_WAIT0(); }
        __syncthreads();

        const __half* sKh = adsm + (t & 1) * ABUF + 0 * ATILE;
        const __half* sVh = adsm + (t & 1) * ABUF + 1 * ATILE;
        const int k0 = t * 64;

        {
            float s[8][4];
#pragma unroll
            for (int nt = 0; nt < 8; nt++)
#pragma unroll
                for (int j = 0; j < 4; j++) s[nt][j] = 0.f;

#pragma unroll
            for (int nt = 0; nt < 8; nt++) {
                if (k0 + nt * 8 <= wlast) {
                    const int ko = (nt * 8 + r8) * AP + 8 * mi;
                    uint32_t bKh[8];
                    ldsm4(bKh,     sKh + ko);
                    ldsm4(bKh + 4, sKh + ko + 32);
#pragma unroll
                    for (int ks = 0; ks < 4; ks++) {
                        mma16816(s[nt], aQh[ks], &bKh[2 * ks]);
                        mma16816(s[nt], aQl[ks], &bKh[2 * ks]);
                    }
                }
            }

            if (k0 + 63 > wr0) {
                const int row0 = wr0 + lr, row1 = wr0 + 8 + lr;
#pragma unroll
                for (int nt = 0; nt < 8; nt++) {
                    int kc = k0 + nt * 8 + 2 * lc;
                    if (kc > row0)     s[nt][0] = -1e30f;
                    if (kc + 1 > row0) s[nt][1] = -1e30f;
                    if (kc > row1)     s[nt][2] = -1e30f;
                    if (kc + 1 > row1) s[nt][3] = -1e30f;
                }
            }

            float tm0 = -1e30f, tm1 = -1e30f;
#pragma unroll
            for (int nt = 0; nt < 8; nt++) {
                tm0 = fmaxf(tm0, fmaxf(s[nt][0], s[nt][1]));
                tm1 = fmaxf(tm1, fmaxf(s[nt][2], s[nt][3]));
            }
            tm0 = fmaxf(tm0, __shfl_xor_sync(0xffffffff, tm0, 1));
            tm0 = fmaxf(tm0, __shfl_xor_sync(0xffffffff, tm0, 2));
            tm1 = fmaxf(tm1, __shfl_xor_sync(0xffffffff, tm1, 1));
            tm1 = fmaxf(tm1, __shfl_xor_sync(0xffffffff, tm1, 2));

            float mn0 = fmaxf(m0, tm0), mn1 = fmaxf(m1, tm1);
            float cr0 = fexp2((m0 - mn0) * L2E);
            float cr1 = fexp2((m1 - mn1) * L2E);
            m0 = mn0; m1 = mn1;
            const float nm0 = -m0 * L2E, nm1 = -m1 * L2E;

            float ls0 = 0.f, ls1 = 0.f;
#pragma unroll
            for (int nt = 0; nt < 8; nt++) {
                s[nt][0] = fexp2(fmaf(s[nt][0], L2E, nm0));
                s[nt][1] = fexp2(fmaf(s[nt][1], L2E, nm0));
                s[nt][2] = fexp2(fmaf(s[nt][2], L2E, nm1));
                s[nt][3] = fexp2(fmaf(s[nt][3], L2E, nm1));
                ls0 += s[nt][0] + s[nt][1];
                ls1 += s[nt][2] + s[nt][3];
            }
            ls0 += __shfl_xor_sync(0xffffffff, ls0, 1);
            ls0 += __shfl_xor_sync(0xffffffff, ls0, 2);
            ls1 += __shfl_xor_sync(0xffffffff, ls1, 1);
            ls1 += __shfl_xor_sync(0xffffffff, ls1, 2);
            l0 = l0 * cr0 + ls0;
            l1 = l1 * cr1 + ls1;
#pragma unroll
            for (int nt = 0; nt < 8; nt++) {
                o[nt][0] *= cr0; o[nt][1] *= cr0;
                o[nt][2] *= cr1; o[nt][3] *= cr1;
            }

            uint32_t pH[4][4], pL[4][4];
#pragma unroll
            for (int ks = 0; ks < 4; ks++) {
                if (k0 + ks * 16 <= wlast) {
                    split_pack_h(s[2*ks][0],   s[2*ks][1],   pH[ks][0], pL[ks][0]);
                    split_pack_h(s[2*ks][2],   s[2*ks][3],   pH[ks][1], pL[ks][1]);
                    split_pack_h(s[2*ks+1][0], s[2*ks+1][1], pH[ks][2], pL[ks][2]);
                    split_pack_h(s[2*ks+1][2], s[2*ks+1][3], pH[ks][3], pL[ks][3]);
                }
            }

#pragma unroll
            for (int dt = 0; dt < 8; dt++) {
                const int vo = lane * AP + dt * 8;
                uint32_t bVh[8];
                ldsm4t(bVh,     sVh + vo);
                ldsm4t(bVh + 4, sVh + vo + 32 * AP);
#pragma unroll
                for (int ks = 0; ks < 4; ks++) {
                    if (k0 + ks * 16 <= wlast) {
                        mma16816(o[dt], pH[ks], &bVh[2 * ks]);
                        mma16816(o[dt], pL[ks], &bVh[2 * ks]);
                    }
                }
            }
        }
        __syncthreads();
    }

    const float i0 = 1.f / l0, i1 = 1.f / l1;
    const int b = bh >> 3;
    const int h = bh & 7;
    const int row0 = wr0 + lr, row1 = wr0 + 8 + lr;
    float* __restrict__ o0 = out + ((size_t)(b * SEQLEN + row0) * DOUT) + h * HDIM;
    float* __restrict__ o1 = out + ((size_t)(b * SEQLEN + row1) * DOUT) + h * HDIM;
#pragma unroll
    for (int nt = 0; nt < 8; nt++) {
        int d = nt * 8 + 2 * lc;
        *(float2*)&o0[d] = make_float2(o[nt][0] * i0, o[nt][1] * i0);
        *(float2*)&o1[d] = make_float2(o[nt][2] * i1, o[nt][3] * i1);
    }
}

// ---------------------------------------------------------------------------
extern "C" void kernel_launch(void* const* d_in, const int* in_sizes, int n_in,
                              void* d_out, int out_size)
{
    const float* Qs = (const float*)d_in[0];
    const float* Ks = (const float*)d_in[1];
    const float* Vs = (const float*)d_in[2];
    const float* WQ = (const float*)d_in[3];
    const float* WK = (const float*)d_in[4];
    const float* WV = (const float*)d_in[5];
    float* out = (float*)d_out;

    static bool attr_done = false;
    if (!attr_done) {
        cudaFuncSetAttribute(proj_mma_sync,
                             cudaFuncAttributeMaxDynamicSharedMemorySize, PROJ_DSMEM);
        cudaFuncSetAttribute(attn_mma,
                             cudaFuncAttributeMaxDynamicSharedMemorySize, ATTN_DSMEM);
        attr_done = true;
    }

    convert_x<<<dim3(MTOT * DIN / 8 / 256, 3), 256>>>(Qs, Ks, Vs);
    convert_wt<<<dim3(DOUT / 32, DIN / 32, 3), dim3(32, 8)>>>(WQ, WK, WV);
    proj_mma_sync<<<dim3(DOUT / 128, MTOT / 128, 3), 256, PROJ_DSMEM>>>();

    attn_mma<<<(SEQLEN / QBLK) * NBH, 128, ATTN_DSMEM>>>(out);
}

// round 12
// speedup vs baseline: 2.4773x; 1.4518x over previous
#include <cuda_runtime.h>
#include <cuda_fp16.h>
#include <cstdint>

#define BATCH 8
#define SEQLEN 1024
#define DIN 512
#define NHEAD 8
#define HDIM 64
#define DOUT 512
#define MTOT (BATCH * SEQLEN)   // 8192
#define NBH (BATCH * NHEAD)     // 64

// ---------------------------------------------------------------------------
// Static device scratch (no runtime allocation allowed)
// ---------------------------------------------------------------------------
__device__ __align__(16) __half g_xh[3 * MTOT * DIN];     // rn(X)
__device__ __align__(16) __half g_wth[3 * DOUT * DIN];    // rn(W^T)

// projected q/k/v, head-major [bh][l][64], rounded fp16
__device__ __align__(16) __half g_qh[NBH * SEQLEN * HDIM];
__device__ __align__(16) __half g_kh[NBH * SEQLEN * HDIM];
__device__ __align__(16) __half g_vh[NBH * SEQLEN * HDIM];

__device__ __forceinline__ void mma16816(float* c, const uint32_t* a, const uint32_t* b) {
    asm volatile(
        "mma.sync.aligned.m16n8k16.row.col.f32.f16.f16.f32 "
        "{%0,%1,%2,%3}, {%4,%5,%6,%7}, {%8,%9}, {%0,%1,%2,%3};"
        : "+f"(c[0]), "+f"(c[1]), "+f"(c[2]), "+f"(c[3])
        : "r"(a[0]), "r"(a[1]), "r"(a[2]), "r"(a[3]), "r"(b[0]), "r"(b[1]));
}

__device__ __forceinline__ void ldsm4(uint32_t* r, const __half* p) {
    uint32_t a = (uint32_t)__cvta_generic_to_shared(p);
    asm volatile("ldmatrix.sync.aligned.m8n8.x4.shared.b16 {%0,%1,%2,%3}, [%4];"
        : "=r"(r[0]), "=r"(r[1]), "=r"(r[2]), "=r"(r[3]) : "r"(a));
}
__device__ __forceinline__ void ldsm4t(uint32_t* r, const __half* p) {
    uint32_t a = (uint32_t)__cvta_generic_to_shared(p);
    asm volatile("ldmatrix.sync.aligned.m8n8.x4.trans.shared.b16 {%0,%1,%2,%3}, [%4];"
        : "=r"(r[0]), "=r"(r[1]), "=r"(r[2]), "=r"(r[3]) : "r"(a));
}

// 16B global->shared async copy
__device__ __forceinline__ void cp16(void* smem_dst, const void* gsrc) {
    uint32_t sa = (uint32_t)__cvta_generic_to_shared(smem_dst);
    asm volatile("cp.async.cg.shared.global [%0], [%1], 16;" :: "r"(sa), "l"(gsrc));
}
#define CP_COMMIT() asm volatile("cp.async.commit_group;" ::: "memory")
#define CP_WAIT1()  asm volatile("cp.async.wait_group 1;" ::: "memory")
#define CP_WAIT0()  asm volatile("cp.async.wait_group 0;" ::: "memory")

// FMA-pipe exp2 (no MUFU), max rel err ~4e-5
__device__ __forceinline__ float fexp2(float t) {
    t = fmaxf(t, -126.0f);
    float z = t + 12582912.0f;
    int   i = __float_as_int(z) - 0x4B400000;
    float f = t - (z - 12582912.0f);
    float p = fmaf(f, 0.00961813f, 0.05550411f);
    p = fmaf(f, p, 0.24022651f);
    p = fmaf(f, p, 0.69314718f);
    p = fmaf(f, p, 1.0f);
    return p * __int_as_float((i + 127) << 23);
}
#define L2E 1.4426950408889634f

__device__ __forceinline__ uint32_t round_pack_h(float x, float y) {
    __half2 H = __halves2half2(__float2half_rn(x), __float2half_rn(y));
    return *(uint32_t*)&H;
}

// ---------------------------------------------------------------------------
// Conversion: X (fp32) -> rn(fp16). 8 floats per thread, 16B stores.
// ---------------------------------------------------------------------------
__global__ __launch_bounds__(256) void convert_x(
    const float* __restrict__ x0, const float* __restrict__ x1,
    const float* __restrict__ x2)
{
    const int sel = blockIdx.y;
    const float* __restrict__ x = (sel == 0) ? x0 : (sel == 1) ? x1 : x2;
    const int i = blockIdx.x * 256 + threadIdx.x;
    const float4* xv = (const float4*)x;
    float4 a = xv[2 * i], b = xv[2 * i + 1];

    uint4 o;
    o.x = round_pack_h(a.x, a.y);
    o.y = round_pack_h(a.z, a.w);
    o.z = round_pack_h(b.x, b.y);
    o.w = round_pack_h(b.z, b.w);
    *(uint4*)&g_xh[(size_t)sel * (MTOT * DIN) + (size_t)i * 8] = o;
}

// W [k][n] fp32 -> transposed rn(fp16) [n][k]
__global__ __launch_bounds__(256) void convert_wt(
    const float* __restrict__ w0, const float* __restrict__ w1,
    const float* __restrict__ w2)
{
    const int sel = blockIdx.z;
    const float* __restrict__ W = (sel == 0) ? w0 : (sel == 1) ? w1 : w2;
    __shared__ float tile[32][33];
    const int n0 = blockIdx.x * 32, k0 = blockIdx.y * 32;
    const int tx = threadIdx.x, ty = threadIdx.y;
#pragma unroll
    for (int i = 0; i < 32; i += 8)
        tile[ty + i][tx] = W[(k0 + ty + i) * DOUT + n0 + tx];
    __syncthreads();
    const size_t base = (size_t)sel * (DOUT * DIN);
#pragma unroll
    for (int i = 0; i < 32; i += 8) {
        int n = ty + i;
        g_wth[base + (size_t)(n0 + n) * DIN + k0 + tx] = __float2half_rn(tile[tx][n]);
    }
}

// ---------------------------------------------------------------------------
// Projection GEMM: single-pass fp16 mma.sync, cp.async double buffer.
// ---------------------------------------------------------------------------
#define PADK 40
#define PTILE (128 * PADK)
#define PBUF  (2 * PTILE)
#define PROJ_DSMEM (2 * PBUF * 2)

__global__ __launch_bounds__(256) void proj_mma_sync()
{
    extern __shared__ __align__(16) __half dsm[];

    const int sel = blockIdx.z;
    const int n0  = blockIdx.x * 128;
    const int m0  = blockIdx.y * 128;
    const int tid = threadIdx.x;
    const int w   = tid >> 5;
    const int lane = tid & 31;
    const int wm = w >> 2, wn = w & 3;
    const int lr = lane >> 2, lc = lane & 3;
    const int mi = lane >> 3, r8 = lane & 7;

    const __half* __restrict__ Ap = g_xh + (size_t)sel * (MTOT * DIN);
    const __half* __restrict__ Bp = g_wth + (size_t)sel * (DOUT * DIN);

    const int r0 = tid >> 2, c0 = (tid & 3) * 8;
    const int r1 = (tid + 256) >> 2, c1 = ((tid + 256) & 3) * 8;

    auto issue = [&](int slab, int buf) {
        const int kk = slab * 32;
        __half* base = dsm + buf * PBUF;
        cp16(base + 0 * PTILE + r0 * PADK + c0, Ap + (size_t)(m0 + r0) * DIN + kk + c0);
        cp16(base + 1 * PTILE + r0 * PADK + c0, Bp + (size_t)(n0 + r0) * DIN + kk + c0);
        cp16(base + 0 * PTILE + r1 * PADK + c1, Ap + (size_t)(m0 + r1) * DIN + kk + c1);
        cp16(base + 1 * PTILE + r1 * PADK + c1, Bp + (size_t)(n0 + r1) * DIN + kk + c1);
        CP_COMMIT();
    };

    const int bofs = (wn * 32 + r8) * PADK + 8 * mi;
    const int aofs = (wm * 64 + (mi & 1) * 8 + r8) * PADK + (mi >> 1) * 8;

    float acc[4][4][4];
#pragma unroll
    for (int i = 0; i < 4; i++)
#pragma unroll
        for (int j = 0; j < 4; j++)
#pragma unroll
            for (int r = 0; r < 4; r++) acc[i][j][r] = 0.f;

    issue(0, 0);

    for (int s = 0; s < DIN / 32; s++) {
        if (s + 1 < DIN / 32) { issue(s + 1, (s + 1) & 1); CP_WAIT1(); }
        else                  { CP_WAIT0(); }
        __syncthreads();

        const __half* sA = dsm + (s & 1) * PBUF + 0 * PTILE;
        const __half* sB = dsm + (s & 1) * PBUF + 1 * PTILE;

        uint32_t bF[4][4];
#pragma unroll
        for (int nt = 0; nt < 4; nt++)
            ldsm4(bF[nt], sB + bofs + nt * 8 * PADK);

#pragma unroll
        for (int ks = 0; ks < 2; ks++) {
            uint32_t af[4][4];
#pragma unroll
            for (int mt = 0; mt < 4; mt++)
                ldsm4(af[mt], sA + aofs + mt * 16 * PADK + ks * 16);
#pragma unroll
            for (int mt = 0; mt < 4; mt++)
#pragma unroll
                for (int nt = 0; nt < 4; nt++)
                    mma16816(acc[mt][nt], af[mt], &bF[nt][2 * ks]);
        }
        __syncthreads();
    }

    const float scale = (sel == 0) ? 0.125f : 1.0f;
    __half* __restrict__ dst = (sel == 0) ? g_qh : (sel == 1) ? g_kh : g_vh;
#pragma unroll
    for (int mt = 0; mt < 4; mt++) {
#pragma unroll
        for (int half = 0; half < 2; half++) {
            int m = m0 + wm * 64 + mt * 16 + half * 8 + lr;
            int b = m >> 10;
            int l = m & 1023;
#pragma unroll
            for (int nt = 0; nt < 4; nt++) {
                int n = n0 + wn * 32 + nt * 8 + lc * 2;
                int h = n >> 6;
                int d = n & 63;
                size_t off = (((size_t)(b * NHEAD + h) * SEQLEN) + l) * HDIM + d;
                *(uint32_t*)&dst[off] =
                    round_pack_h(acc[mt][nt][half * 2 + 0] * scale,
                                 acc[mt][nt][half * 2 + 1] * scale);
            }
        }
    }
}

// ---------------------------------------------------------------------------
// Flash attention: single-pass fp16. 128-thread CTAs (64 q rows), 3 CTAs/SM.
// K row-major; V transposed in the load unit via ldmatrix.trans.
// ---------------------------------------------------------------------------
#define AP 72
#define ATILE (64 * AP)
#define ABUF  (2 * ATILE)
#define ATTN_DSMEM (2 * ABUF * 2)
#define QBLK 64

__global__ __launch_bounds__(128, 3) void attn_mma(float* __restrict__ out)
{
    extern __shared__ __align__(16) __half adsm[];

    const int bh  = blockIdx.x & (NBH - 1);
    const int qb  = (SEQLEN / QBLK - 1) - (blockIdx.x >> 6);
    const int q0  = qb * QBLK;
    const int tid = threadIdx.x;
    const int w    = tid >> 5;
    const int lane = tid & 31;
    const int lr = lane >> 2, lc = lane & 3;
    const int mi = lane >> 3, r8 = lane & 7;
    const int wr0 = q0 + w * 16;
    const int wlast = wr0 + 15;

    const size_t bhoff = (size_t)bh * (SEQLEN * HDIM);
    const __half* __restrict__ Kh = g_kh + bhoff;
    const __half* __restrict__ Vh = g_vh + bhoff;

    auto issue = [&](int tileidx, int buf) {
        const int k0 = tileidx * 64;
        __half* base = adsm + buf * ABUF;
#pragma unroll
        for (int i = 0; i < 4; i++) {
            int idx = tid + i * 128;
            int r = idx >> 3;
            int c = (idx & 7) * 8;
            const size_t g = (size_t)(k0 + r) * HDIM + c;
            const int sm = r * AP + c;
            cp16(base + 0 * ATILE + sm, Kh + g);
            cp16(base + 1 * ATILE + sm, Vh + g);
        }
        CP_COMMIT();
    };

    uint32_t aQ[4][4];
    {
        const __half* __restrict__ Qh = g_qh + bhoff;
#pragma unroll
        for (int ks = 0; ks < 4; ks++) {
            int k = ks * 16 + 2 * lc;
            aQ[ks][0] = *(const uint32_t*)&Qh[(wr0 + lr) * HDIM + k];
            aQ[ks][1] = *(const uint32_t*)&Qh[(wr0 + 8 + lr) * HDIM + k];
            aQ[ks][2] = *(const uint32_t*)&Qh[(wr0 + lr) * HDIM + k + 8];
            aQ[ks][3] = *(const uint32_t*)&Qh[(wr0 + 8 + lr) * HDIM + k + 8];
        }
    }

    float o[8][4];
#pragma unroll
    for (int nt = 0; nt < 8; nt++)
#pragma unroll
        for (int j = 0; j < 4; j++) o[nt][j] = 0.f;
    float m0 = -1e30f, m1 = -1e30f, l0 = 0.f, l1 = 0.f;

    const int ntiles = qb + 1;
    issue(0, 0);

    for (int t = 0; t < ntiles; t++) {
        if (t + 1 < ntiles) { issue(t + 1, (t + 1) & 1); CP_WAIT1(); }
        else                { CP_WAIT0(); }
        __syncthreads();

        const __half* sKh = adsm + (t & 1) * ABUF + 0 * ATILE;
        const __half* sVh = adsm + (t & 1) * ABUF + 1 * ATILE;
        const int k0 = t * 64;

        {
            float s[8][4];
#pragma unroll
            for (int nt = 0; nt < 8; nt++)
#pragma unroll
                for (int j = 0; j < 4; j++) s[nt][j] = 0.f;

#pragma unroll
            for (int nt = 0; nt < 8; nt++) {
                if (k0 + nt * 8 <= wlast) {
                    const int ko = (nt * 8 + r8) * AP + 8 * mi;
                    uint32_t bK[8];
                    ldsm4(bK,     sKh + ko);
                    ldsm4(bK + 4, sKh + ko + 32);
#pragma unroll
                    for (int ks = 0; ks < 4; ks++)
                        mma16816(s[nt], aQ[ks], &bK[2 * ks]);
                }
            }

            if (k0 + 63 > wr0) {
                const int row0 = wr0 + lr, row1 = wr0 + 8 + lr;
#pragma unroll
                for (int nt = 0; nt < 8; nt++) {
                    int kc = k0 + nt * 8 + 2 * lc;
                    if (kc > row0)     s[nt][0] = -1e30f;
                    if (kc + 1 > row0) s[nt][1] = -1e30f;
                    if (kc > row1)     s[nt][2] = -1e30f;
                    if (kc + 1 > row1) s[nt][3] = -1e30f;
                }
            }

            float tm0 = -1e30f, tm1 = -1e30f;
#pragma unroll
            for (int nt = 0; nt < 8; nt++) {
                tm0 = fmaxf(tm0, fmaxf(s[nt][0], s[nt][1]));
                tm1 = fmaxf(tm1, fmaxf(s[nt][2], s[nt][3]));
            }
            tm0 = fmaxf(tm0, __shfl_xor_sync(0xffffffff, tm0, 1));
            tm0 = fmaxf(tm0, __shfl_xor_sync(0xffffffff, tm0, 2));
            tm1 = fmaxf(tm1, __shfl_xor_sync(0xffffffff, tm1, 1));
            tm1 = fmaxf(tm1, __shfl_xor_sync(0xffffffff, tm1, 2));

            float mn0 = fmaxf(m0, tm0), mn1 = fmaxf(m1, tm1);
            float cr0 = fexp2((m0 - mn0) * L2E);
            float cr1 = fexp2((m1 - mn1) * L2E);
            m0 = mn0; m1 = mn1;
            const float nm0 = -m0 * L2E, nm1 = -m1 * L2E;

            float ls0 = 0.f, ls1 = 0.f;
#pragma unroll
            for (int nt = 0; nt < 8; nt++) {
                s[nt][0] = fexp2(fmaf(s[nt][0], L2E, nm0));
                s[nt][1] = fexp2(fmaf(s[nt][1], L2E, nm0));
                s[nt][2] = fexp2(fmaf(s[nt][2], L2E, nm1));
                s[nt][3] = fexp2(fmaf(s[nt][3], L2E, nm1));
                ls0 += s[nt][0] + s[nt][1];
                ls1 += s[nt][2] + s[nt][3];
            }
            ls0 += __shfl_xor_sync(0xffffffff, ls0, 1);
            ls0 += __shfl_xor_sync(0xffffffff, ls0, 2);
            ls1 += __shfl_xor_sync(0xffffffff, ls1, 1);
            ls1 += __shfl_xor_sync(0xffffffff, ls1, 2);
            l0 = l0 * cr0 + ls0;
            l1 = l1 * cr1 + ls1;
#pragma unroll
            for (int nt = 0; nt < 8; nt++) {
                o[nt][0] *= cr0; o[nt][1] *= cr0;
                o[nt][2] *= cr1; o[nt][3] *= cr1;
            }

            uint32_t pF[4][4];
#pragma unroll
            for (int ks = 0; ks < 4; ks++) {
                if (k0 + ks * 16 <= wlast) {
                    pF[ks][0] = round_pack_h(s[2*ks][0],   s[2*ks][1]);
                    pF[ks][1] = round_pack_h(s[2*ks][2],   s[2*ks][3]);
                    pF[ks][2] = round_pack_h(s[2*ks+1][0], s[2*ks+1][1]);
                    pF[ks][3] = round_pack_h(s[2*ks+1][2], s[2*ks+1][3]);
                }
            }

#pragma unroll
            for (int dt = 0; dt < 8; dt++) {
                const int vo = lane * AP + dt * 8;
                uint32_t bV[8];
                ldsm4t(bV,     sVh + vo);
                ldsm4t(bV + 4, sVh + vo + 32 * AP);
#pragma unroll
                for (int ks = 0; ks < 4; ks++)
                    if (k0 + ks * 16 <= wlast)
                        mma16816(o[dt], pF[ks], &bV[2 * ks]);
            }
        }
        __syncthreads();
    }

    const float i0 = 1.f / l0, i1 = 1.f / l1;
    const int b = bh >> 3;
    const int h = bh & 7;
    const int row0 = wr0 + lr, row1 = wr0 + 8 + lr;
    float* __restrict__ o0 = out + ((size_t)(b * SEQLEN + row0) * DOUT) + h * HDIM;
    float* __restrict__ o1 = out + ((size_t)(b * SEQLEN + row1) * DOUT) + h * HDIM;
#pragma unroll
    for (int nt = 0; nt < 8; nt++) {
        int d = nt * 8 + 2 * lc;
        *(float2*)&o0[d] = make_float2(o[nt][0] * i0, o[nt][1] * i0);
        *(float2*)&o1[d] = make_float2(o[nt][2] * i1, o[nt][3] * i1);
    }
}

// ---------------------------------------------------------------------------
extern "C" void kernel_launch(void* const* d_in, const int* in_sizes, int n_in,
                              void* d_out, int out_size)
{
    const float* Qs = (const float*)d_in[0];
    const float* Ks = (const float*)d_in[1];
    const float* Vs = (const float*)d_in[2];
    const float* WQ = (const float*)d_in[3];
    const float* WK = (const float*)d_in[4];
    const float* WV = (const float*)d_in[5];
    float* out = (float*)d_out;

    static bool attr_done = false;
    if (!attr_done) {
        cudaFuncSetAttribute(proj_mma_sync,
                             cudaFuncAttributeMaxDynamicSharedMemorySize, PROJ_DSMEM);
        cudaFuncSetAttribute(attn_mma,
                             cudaFuncAttributeMaxDynamicSharedMemorySize, ATTN_DSMEM);
        attr_done = true;
    }

    convert_x<<<dim3(MTOT * DIN / 8 / 256, 3), 256>>>(Qs, Ks, Vs);
    convert_wt<<<dim3(DOUT / 32, DIN / 32, 3), dim3(32, 8)>>>(WQ, WK, WV);
    proj_mma_sync<<<dim3(DOUT / 128, MTOT / 128, 3), 256, PROJ_DSMEM>>>();

    attn_mma<<<(SEQLEN / QBLK) * NBH, 128, ATTN_DSMEM>>>(out);
}